// round 11
// baseline (speedup 1.0000x reference)
#include <cuda_runtime.h>
#include <cstdint>

#define NROW 8192

// ---------------- scratch ----------------
__device__ float g_Wm [NROW*64];         // pair-interleaved cols, tf32
__device__ float g_Wv [NROW*96];
__device__ float g_XFm[NROW*64];
__device__ float g_XFv[NROW*96];
__device__ float g_Lp [2][4][NROW*32];   // lambda partials (fp32)
__device__ float g_LTm[32*NROW];         // Lambda^T, col-interleaved, tf32
__device__ float g_LTv[32*NROW];
__device__ float g_QNm[NROW];
__device__ float g_QNv[NROW];
__device__ float g_XNm[NROW];
__device__ float g_XNv[NROW];
__device__ float g_Zp [2][4][NROW*32];   // fused z partials (path, x-quarter)

__device__ __forceinline__ unsigned f2tf(float x){
  unsigned r; asm("cvt.rna.tf32.f32 %0, %1;" : "=r"(r) : "f"(x)); return r;
}
__device__ __forceinline__ float tf2f(float x){ return __uint_as_float(f2tf(x)); }
__device__ __forceinline__ float ex2f(float x){
  float r; asm("ex2.approx.f32 %0, %1;" : "=f"(r) : "f"(x)); return r;
}
__device__ __forceinline__ unsigned fbits(float x){ return __float_as_uint(x); }
__device__ __forceinline__ void mma8(float* c, unsigned a0,unsigned a1,unsigned a2,unsigned a3,
                                     unsigned b0,unsigned b1){
  asm volatile("mma.sync.aligned.m16n8k8.row.col.f32.tf32.tf32.f32 "
               "{%0,%1,%2,%3},{%4,%5,%6,%7},{%8,%9},{%0,%1,%2,%3};\n"
               : "+f"(c[0]), "+f"(c[1]), "+f"(c[2]), "+f"(c[3])
               : "r"(a0), "r"(a1), "r"(a2), "r"(a3), "r"(b0), "r"(b1));
}
__device__ __forceinline__ void cpa16(void* dst, const void* src){
  unsigned d = (unsigned)__cvta_generic_to_shared(dst);
  asm volatile("cp.async.cg.shared.global [%0], [%1], 16;\n" :: "r"(d), "l"(src));
}
__device__ __forceinline__ void cpa_commit(){ asm volatile("cp.async.commit_group;\n"); }
__device__ __forceinline__ void cpa_wait0(){ asm volatile("cp.async.wait_group 0;\n"); }
__device__ __forceinline__ void cpa_wait1(){ asm volatile("cp.async.wait_group 1;\n"); }

// pair-interleave within 8-groups: orig offset j -> 2*(j&3) + ((j&4)>>2)
__device__ __forceinline__ int ilv(int j){ return (j & ~7) + 2*(j&3) + ((j&4)>>2); }

// ---------------- 1) prep ----------------
__global__ __launch_bounds__(256) void prep_kernel(
    const float* __restrict__ x_mu, const float* __restrict__ y_eta,
    const float* __restrict__ y_mean, const float* __restrict__ y_var,
    const float* __restrict__ X_mean, const float* __restrict__ X_var){
  int row  = blockIdx.x*8 + (threadIdx.x>>5);
  int lane = threadIdx.x & 31;
  int il   = ilv(lane);
  float xm = x_mu [row*32+lane];
  float s  = y_mean[row*32+lane] + y_var[row*32+lane];
  float fe = 0.01f * y_eta[(NROW-1-row)*32+lane];
  g_Wm[row*64+il]    = tf2f(xm);
  g_Wm[row*64+32+il] = tf2f(s);
  g_Wv[row*96+il]    = tf2f(xm);
  g_Wv[row*96+32+il] = tf2f(fe);
  g_Wv[row*96+64+il] = tf2f(s);
  float qm = xm*xm + s*s;
  float qv = qm + fe*fe;
  float a  = X_mean[row*64+lane], bm = X_mean[row*64+32+lane];
  g_XFm[row*64+il]    = tf2f(a);
  g_XFm[row*64+32+il] = tf2f(bm);
  float nm = a*a + bm*bm;
  float c0 = X_var[row*96+lane], c1 = X_var[row*96+32+lane], c2 = X_var[row*96+64+lane];
  g_XFv[row*96+il]    = tf2f(c0);
  g_XFv[row*96+32+il] = tf2f(c1);
  g_XFv[row*96+64+il] = tf2f(c2);
  float nv = c0*c0 + c1*c1 + c2*c2;
  #pragma unroll
  for(int o=16;o;o>>=1){
    qm += __shfl_xor_sync(0xffffffffu,qm,o);
    qv += __shfl_xor_sync(0xffffffffu,qv,o);
    nm += __shfl_xor_sync(0xffffffffu,nm,o);
    nv += __shfl_xor_sync(0xffffffffu,nv,o);
  }
  if(lane==0){ g_QNm[row]=qm; g_QNv[row]=qv; g_XNm[row]=nm; g_XNv[row]=nv; }
}

// ---------------- 2) Lambda partials (K-split x4, cp.async 2-stage) ----------------
__global__ __launch_bounds__(128) void lambda_kernel(
    const float* __restrict__ Am, const float* __restrict__ Av,
    const float* __restrict__ Zm, const float* __restrict__ Zv){
  int path = blockIdx.z, ks = blockIdx.y;
  const float* A = path ? Av : Am;
  const float* Z = path ? Zv : Zm;
  float* L = &g_Lp[path][ks][0];
  __shared__ float As[2][64*36];
  __shared__ float Zs[2][32*40];
  int tid=threadIdx.x, w=tid>>5, lane=tid&31, gr=lane>>2, p=lane&3;
  int rb = blockIdx.x*64, kbase = ks*2048;

  auto load = [&](int st, int k0){
    #pragma unroll
    for(int i=0;i<4;i++){
      int idx=tid+128*i; int r=idx>>3, c4=idx&7;
      cpa16(&As[st][r*36+c4*4], &A[(size_t)(rb+r)*NROW + k0 + c4*4]);
    }
    #pragma unroll
    for(int i=0;i<2;i++){
      int idx=tid+128*i; int r=idx>>3, c4=idx&7;
      cpa16(&Zs[st][r*40+c4*4], &Z[(size_t)(k0+r)*32 + c4*4]);
    }
  };

  load(0, kbase); cpa_commit();
  float acc[16];
  #pragma unroll
  for(int i=0;i<16;i++) acc[i]=0.f;

  for(int kt=0;kt<64;kt++){
    if(kt<63){ load((kt+1)&1, kbase+(kt+1)*32); cpa_commit(); cpa_wait1(); }
    else cpa_wait0();
    __syncthreads();
    const float* Ax = As[kt&1];
    const float* Zx = Zs[kt&1];
    #pragma unroll
    for(int kc=0;kc<4;kc++){
      unsigned a0=f2tf(Ax[(w*16+gr  )*36 + kc*8+p  ]);
      unsigned a1=f2tf(Ax[(w*16+gr+8)*36 + kc*8+p  ]);
      unsigned a2=f2tf(Ax[(w*16+gr  )*36 + kc*8+p+4]);
      unsigned a3=f2tf(Ax[(w*16+gr+8)*36 + kc*8+p+4]);
      #pragma unroll
      for(int nt=0;nt<4;nt++){
        unsigned b0=f2tf(Zx[(kc*8+p  )*40 + nt*8+gr]);
        unsigned b1=f2tf(Zx[(kc*8+p+4)*40 + nt*8+gr]);
        mma8(&acc[nt*4], a0,a1,a2,a3, b0,b1);
      }
    }
    __syncthreads();
  }
  int q = rb + w*16 + gr;
  #pragma unroll
  for(int nt=0;nt<4;nt++){
    L[ q   *32 + nt*8 + 2*p  ] = acc[nt*4+0];
    L[ q   *32 + nt*8 + 2*p+1] = acc[nt*4+1];
    L[(q+8)*32 + nt*8 + 2*p  ] = acc[nt*4+2];
    L[(q+8)*32 + nt*8 + 2*p+1] = acc[nt*4+3];
  }
}

// ---------------- 2b) reduce partials -> Lambda^T interleaved ----------------
__global__ __launch_bounds__(256) void reduce_kernel(){
  int path = blockIdx.y;
  int idx  = blockIdx.x*256 + threadIdx.x;
  int r = idx>>3, c4 = idx&7;
  float4 s0 = *(const float4*)&g_Lp[path][0][idx*4];
  float4 s1 = *(const float4*)&g_Lp[path][1][idx*4];
  float4 s2 = *(const float4*)&g_Lp[path][2][idx*4];
  float4 s3 = *(const float4*)&g_Lp[path][3][idx*4];
  float vx = s0.x+s1.x+s2.x+s3.x;
  float vy = s0.y+s1.y+s2.y+s3.y;
  float vz = s0.z+s1.z+s2.z+s3.z;
  float vw = s0.w+s1.w+s2.w+s3.w;
  int pos = ilv(r);
  float* LT = path ? g_LTv : g_LTm;
  LT[(c4*4+0)*NROW + pos] = tf2f(vx);
  LT[(c4*4+1)*NROW + pos] = tf2f(vy);
  LT[(c4*4+2)*NROW + pos] = tf2f(vz);
  LT[(c4*4+3)*NROW + pos] = tf2f(vw);
}

// ---------------- 3) fused scores -> exp -> PV (x-quarter split) ----------------
// 8 warps, M=16/warp, each warp does all 4 xs sub-tiles; 16 x-tiles per block.
template<int D>
__device__ __forceinline__ void fused_body(
    const float* __restrict__ Wf, const float* __restrict__ XF,
    const float* __restrict__ LTg, const float* __restrict__ QN,
    const float* __restrict__ XN, float* __restrict__ Zout, int qblk, int xq){
  extern __shared__ float sm[];
  const int SD = D + 8;
  float* Xs0 = sm;
  float* Xs1 = Xs0 + 128*SD;
  float* LT0 = Xs1 + 128*SD;            // Lambda tile, 32 x 136
  float* LT1 = LT0 + 32*136;
  float* xn0 = LT1 + 32*136;
  float* xn1 = xn0 + 128;
  float* Kt  = xn1 + 128;               // 8 warps x (16x40)
  int tid=threadIdx.x, w=tid>>5, lane=tid&31, gr=lane>>2, p=lane&3;
  int rbase = w*16;
  float* Kw = Kt + w*(16*40);
  int q0 = qblk*128;
  const int NF4 = 128*(D/4);

  // ---- prologue: W tile -> A-frags ----
  for(int i=tid;i<NF4;i+=256){
    int r=i/(D/4), c4=i%(D/4);
    cpa16(&Xs0[r*SD+c4*4], &Wf[(size_t)(q0+r)*D + c4*4]);
  }
  cpa_commit(); cpa_wait0(); __syncthreads();
  unsigned wa[D/8][4];
  #pragma unroll
  for(int kk=0;kk<D/8;kk++){
    float2 lo = *(float2*)&Xs0[(rbase+gr  )*SD + kk*8+2*p];
    float2 hi = *(float2*)&Xs0[(rbase+gr+8)*SD + kk*8+2*p];
    wa[kk][0]=fbits(lo.x); wa[kk][1]=fbits(hi.x);
    wa[kk][2]=fbits(lo.y); wa[kk][3]=fbits(hi.y);
  }
  float qn0=QN[q0+rbase+gr], qn1=QN[q0+rbase+gr+8];
  __syncthreads();

  float z[16];
  #pragma unroll
  for(int i=0;i<16;i++) z[i]=0.f;
  const float CL = 1.1271055e-2f;       // log2(e)/128

  auto load_tile = [&](float* Xd, float* Ld, float* xd, int xb){
    for(int i=tid;i<NF4;i+=256){
      int r=i/(D/4), c4=i%(D/4);
      cpa16(&Xd[r*SD+c4*4], &XF[(size_t)(xb+r)*D + c4*4]);
    }
    for(int i=tid;i<1024;i+=256){
      int c=i>>5, ch=i&31;
      cpa16(&Ld[c*136+ch*4], &LTg[(size_t)c*NROW + xb + ch*4]);
    }
    if(tid<32) cpa16(&xd[tid*4], &XN[xb+tid*4]);
  };

  int xbase = xq*16;                    // this block's 16 x-tiles
  load_tile(Xs0, LT0, xn0, xbase*128); cpa_commit();

  for(int t=0;t<16;t++){
    cpa_wait0(); __syncthreads();
    if(t<15){
      if(t&1) load_tile(Xs0, LT0, xn0, (xbase+t+1)*128);
      else    load_tile(Xs1, LT1, xn1, (xbase+t+1)*128);
      cpa_commit();
    }
    float* X_  = (t&1)? Xs1 : Xs0;
    float* L_  = (t&1)? LT1 : LT0;
    float* xn_ = (t&1)? xn1 : xn0;
    #pragma unroll
    for(int xs=0; xs<4; xs++){
      float s[16];
      #pragma unroll
      for(int i=0;i<16;i++) s[i]=0.f;
      #pragma unroll
      for(int kk=0;kk<D/8;kk++){
        #pragma unroll
        for(int nt=0;nt<4;nt++){
          float2 b = *(float2*)&X_[(xs*32+nt*8+gr)*SD + kk*8+2*p];
          mma8(&s[nt*4], wa[kk][0],wa[kk][1],wa[kk][2],wa[kk][3], fbits(b.x),fbits(b.y));
        }
      }
      int pb = (p<2)? 4*p : 4*p-7;      // interleaved store base for cols 2p,2p+1
      #pragma unroll
      for(int nt=0;nt<4;nt++){
        float xnA=xn_[xs*32+nt*8+2*p], xnB=xn_[xs*32+nt*8+2*p+1];
        Kw[(gr  )*40+nt*8+pb  ]=tf2f(ex2f(fminf(2.f*s[nt*4+0]-qn0-xnA,0.f)*CL));
        Kw[(gr  )*40+nt*8+pb+2]=tf2f(ex2f(fminf(2.f*s[nt*4+1]-qn0-xnB,0.f)*CL));
        Kw[(gr+8)*40+nt*8+pb  ]=tf2f(ex2f(fminf(2.f*s[nt*4+2]-qn1-xnA,0.f)*CL));
        Kw[(gr+8)*40+nt*8+pb+2]=tf2f(ex2f(fminf(2.f*s[nt*4+3]-qn1-xnB,0.f)*CL));
      }
      __syncwarp();
      #pragma unroll
      for(int kc=0;kc<4;kc++){
        float2 Al=*(float2*)&Kw[(gr  )*40+kc*8+2*p];
        float2 Ah=*(float2*)&Kw[(gr+8)*40+kc*8+2*p];
        #pragma unroll
        for(int nt=0;nt<4;nt++){
          float2 b=*(float2*)&L_[(nt*8+gr)*136 + xs*32 + kc*8+2*p];
          mma8(&z[nt*4], fbits(Al.x),fbits(Ah.x),fbits(Al.y),fbits(Ah.y),
               fbits(b.x),fbits(b.y));
        }
      }
      __syncwarp();
    }
  }

  // ---- write z partial (each warp owns its 16 rows) ----
  #pragma unroll
  for(int nt=0;nt<4;nt++){
    *(float2*)&Zout[(size_t)(q0+rbase+gr  )*32 + nt*8+2*p] = make_float2(z[nt*4+0], z[nt*4+1]);
    *(float2*)&Zout[(size_t)(q0+rbase+gr+8)*32 + nt*8+2*p] = make_float2(z[nt*4+2], z[nt*4+3]);
  }
}

__global__ __launch_bounds__(256,1) void fused_kernel(){
  int id = blockIdx.x;
  int qblk = id & 63, xq = (id>>6)&3;
  if(id < 256) fused_body<96>(g_Wv,g_XFv,g_LTv,g_QNv,g_XNv,&g_Zp[1][xq][0],qblk,xq);
  else         fused_body<64>(g_Wm,g_XFm,g_LTm,g_QNm,g_XNm,&g_Zp[0][xq][0],qblk,xq);
}

// ---------------- 4) finalize: out = y_mean + y_var + sum of 8 z partials ----------------
__global__ __launch_bounds__(256) void final_kernel(
    const float* __restrict__ y_mean, const float* __restrict__ y_var,
    float* __restrict__ out){
  int i = blockIdx.x*256 + threadIdx.x;
  float4 a=*(const float4*)&y_mean[i*4];
  float4 b=*(const float4*)&y_var [i*4];
  float ox=a.x+b.x, oy=a.y+b.y, oz=a.z+b.z, ow=a.w+b.w;
  #pragma unroll
  for(int pth=0;pth<2;pth++)
    #pragma unroll
    for(int xq=0;xq<4;xq++){
      float4 zp=*(const float4*)&g_Zp[pth][xq][i*4];
      ox+=zp.x; oy+=zp.y; oz+=zp.z; ow+=zp.w;
    }
  float4 o; o.x=ox; o.y=oy; o.z=oz; o.w=ow;
  *(float4*)&out[i*4]=o;
}

extern "C" void kernel_launch(void* const* d_in, const int* in_sizes, int n_in,
                              void* d_out, int out_size){
  const float* x_mu   = (const float*)d_in[0];
  const float* y_eta  = (const float*)d_in[1];
  const float* y_mean = (const float*)d_in[2];
  const float* y_var  = (const float*)d_in[3];
  const float* X_mean = (const float*)d_in[4];
  const float* X_var  = (const float*)d_in[5];
  const float* Z_mean = (const float*)d_in[6];
  const float* Z_var  = (const float*)d_in[7];
  const float* kMinv  = (const float*)d_in[8];
  const float* kVinv  = (const float*)d_in[9];
  float* out = (float*)d_out;

  prep_kernel<<<NROW/8, 256>>>(x_mu, y_eta, y_mean, y_var, X_mean, X_var);
  lambda_kernel<<<dim3(NROW/64,4,2), 128>>>(kMinv, kVinv, Z_mean, Z_var);
  reduce_kernel<<<dim3(256,2), 256>>>();
  // smem (D=96 worst case): 2*128*104 + 2*32*136 + 2*128 + 8*16*40 floats = 162816 B
  const int FSM = (2*128*104 + 2*32*136 + 2*128 + 8*16*40)*4;
  cudaFuncSetAttribute(fused_kernel, cudaFuncAttributeMaxDynamicSharedMemorySize, FSM);
  fused_kernel<<<512, 256, FSM>>>();
  final_kernel<<<NROW*32/4/256, 256>>>(y_mean, y_var, out);
}

// round 12
// speedup vs baseline: 1.1903x; 1.1903x over previous
#include <cuda_runtime.h>
#include <cuda_bf16.h>
#include <cstdint>

#define NROW 8192

// ---------------- scratch ----------------
__device__ __nv_bfloat16 g_Wm [NROW*64];   // plain row-major bf16
__device__ __nv_bfloat16 g_Wv [NROW*96];
__device__ __nv_bfloat16 g_XFm[NROW*64];
__device__ __nv_bfloat16 g_XFv[NROW*96];
__device__ float g_Lp [2][4][NROW*32];     // lambda partials (fp32)
__device__ float g_LTm[32*NROW];           // Lambda^T, col-interleaved, tf32
__device__ float g_LTv[32*NROW];
__device__ float g_QNm[NROW];
__device__ float g_QNv[NROW];
__device__ float g_XNm[NROW];
__device__ float g_XNv[NROW];
__device__ float g_Zm [NROW*32];
__device__ float g_Zv [NROW*32];

__device__ __forceinline__ unsigned f2tf(float x){
  unsigned r; asm("cvt.rna.tf32.f32 %0, %1;" : "=r"(r) : "f"(x)); return r;
}
__device__ __forceinline__ float tf2f(float x){ return __uint_as_float(f2tf(x)); }
__device__ __forceinline__ float ex2f(float x){
  float r; asm("ex2.approx.f32 %0, %1;" : "=f"(r) : "f"(x)); return r;
}
__device__ __forceinline__ unsigned fbits(float x){ return __float_as_uint(x); }
// tf32 k8 mma (PV + lambda)
__device__ __forceinline__ void mma8(float* c, unsigned a0,unsigned a1,unsigned a2,unsigned a3,
                                     unsigned b0,unsigned b1){
  asm volatile("mma.sync.aligned.m16n8k8.row.col.f32.tf32.tf32.f32 "
               "{%0,%1,%2,%3},{%4,%5,%6,%7},{%8,%9},{%0,%1,%2,%3};\n"
               : "+f"(c[0]), "+f"(c[1]), "+f"(c[2]), "+f"(c[3])
               : "r"(a0), "r"(a1), "r"(a2), "r"(a3), "r"(b0), "r"(b1));
}
// bf16 k16 mma (score)
__device__ __forceinline__ void mma16(float* c, unsigned a0,unsigned a1,unsigned a2,unsigned a3,
                                      unsigned b0,unsigned b1){
  asm volatile("mma.sync.aligned.m16n8k16.row.col.f32.bf16.bf16.f32 "
               "{%0,%1,%2,%3},{%4,%5,%6,%7},{%8,%9},{%0,%1,%2,%3};\n"
               : "+f"(c[0]), "+f"(c[1]), "+f"(c[2]), "+f"(c[3])
               : "r"(a0), "r"(a1), "r"(a2), "r"(a3), "r"(b0), "r"(b1));
}
__device__ __forceinline__ void cpa16(void* dst, const void* src){
  unsigned d = (unsigned)__cvta_generic_to_shared(dst);
  asm volatile("cp.async.cg.shared.global [%0], [%1], 16;\n" :: "r"(d), "l"(src));
}
__device__ __forceinline__ void cpa_commit(){ asm volatile("cp.async.commit_group;\n"); }
__device__ __forceinline__ void cpa_wait0(){ asm volatile("cp.async.wait_group 0;\n"); }
__device__ __forceinline__ void cpa_wait1(){ asm volatile("cp.async.wait_group 1;\n"); }

// pair-interleave within 8-groups (Lambda only): j -> 2*(j&3) + ((j&4)>>2)
__device__ __forceinline__ int ilv(int j){ return (j & ~7) + 2*(j&3) + ((j&4)>>2); }

// ---------------- 1) prep ----------------
__global__ __launch_bounds__(256) void prep_kernel(
    const float* __restrict__ x_mu, const float* __restrict__ y_eta,
    const float* __restrict__ y_mean, const float* __restrict__ y_var,
    const float* __restrict__ X_mean, const float* __restrict__ X_var){
  int row  = blockIdx.x*8 + (threadIdx.x>>5);
  int lane = threadIdx.x & 31;
  float xm = x_mu [row*32+lane];
  float s  = y_mean[row*32+lane] + y_var[row*32+lane];
  float fe = 0.01f * y_eta[(NROW-1-row)*32+lane];
  g_Wm[row*64+lane]    = __float2bfloat16_rn(xm);
  g_Wm[row*64+32+lane] = __float2bfloat16_rn(s);
  g_Wv[row*96+lane]    = __float2bfloat16_rn(xm);
  g_Wv[row*96+32+lane] = __float2bfloat16_rn(fe);
  g_Wv[row*96+64+lane] = __float2bfloat16_rn(s);
  float qm = xm*xm + s*s;
  float qv = qm + fe*fe;
  float a  = X_mean[row*64+lane], bm = X_mean[row*64+32+lane];
  g_XFm[row*64+lane]    = __float2bfloat16_rn(a);
  g_XFm[row*64+32+lane] = __float2bfloat16_rn(bm);
  float nm = a*a + bm*bm;
  float c0 = X_var[row*96+lane], c1 = X_var[row*96+32+lane], c2 = X_var[row*96+64+lane];
  g_XFv[row*96+lane]    = __float2bfloat16_rn(c0);
  g_XFv[row*96+32+lane] = __float2bfloat16_rn(c1);
  g_XFv[row*96+64+lane] = __float2bfloat16_rn(c2);
  float nv = c0*c0 + c1*c1 + c2*c2;
  #pragma unroll
  for(int o=16;o;o>>=1){
    qm += __shfl_xor_sync(0xffffffffu,qm,o);
    qv += __shfl_xor_sync(0xffffffffu,qv,o);
    nm += __shfl_xor_sync(0xffffffffu,nm,o);
    nv += __shfl_xor_sync(0xffffffffu,nv,o);
  }
  if(lane==0){ g_QNm[row]=qm; g_QNv[row]=qv; g_XNm[row]=nm; g_XNv[row]=nv; }
}

// ---------------- 2) Lambda partials (unchanged; tf32 for precision) ----------------
__global__ __launch_bounds__(128) void lambda_kernel(
    const float* __restrict__ Am, const float* __restrict__ Av,
    const float* __restrict__ Zm, const float* __restrict__ Zv){
  int path = blockIdx.z, ks = blockIdx.y;
  const float* A = path ? Av : Am;
  const float* Z = path ? Zv : Zm;
  float* L = &g_Lp[path][ks][0];
  __shared__ float As[2][64*36];
  __shared__ float Zs[2][32*40];
  int tid=threadIdx.x, w=tid>>5, lane=tid&31, gr=lane>>2, p=lane&3;
  int rb = blockIdx.x*64, kbase = ks*2048;

  auto load = [&](int st, int k0){
    #pragma unroll
    for(int i=0;i<4;i++){
      int idx=tid+128*i; int r=idx>>3, c4=idx&7;
      cpa16(&As[st][r*36+c4*4], &A[(size_t)(rb+r)*NROW + k0 + c4*4]);
    }
    #pragma unroll
    for(int i=0;i<2;i++){
      int idx=tid+128*i; int r=idx>>3, c4=idx&7;
      cpa16(&Zs[st][r*40+c4*4], &Z[(size_t)(k0+r)*32 + c4*4]);
    }
  };

  load(0, kbase); cpa_commit();
  float acc[16];
  #pragma unroll
  for(int i=0;i<16;i++) acc[i]=0.f;

  for(int kt=0;kt<64;kt++){
    if(kt<63){ load((kt+1)&1, kbase+(kt+1)*32); cpa_commit(); cpa_wait1(); }
    else cpa_wait0();
    __syncthreads();
    const float* Ax = As[kt&1];
    const float* Zx = Zs[kt&1];
    #pragma unroll
    for(int kc=0;kc<4;kc++){
      unsigned a0=f2tf(Ax[(w*16+gr  )*36 + kc*8+p  ]);
      unsigned a1=f2tf(Ax[(w*16+gr+8)*36 + kc*8+p  ]);
      unsigned a2=f2tf(Ax[(w*16+gr  )*36 + kc*8+p+4]);
      unsigned a3=f2tf(Ax[(w*16+gr+8)*36 + kc*8+p+4]);
      #pragma unroll
      for(int nt=0;nt<4;nt++){
        unsigned b0=f2tf(Zx[(kc*8+p  )*40 + nt*8+gr]);
        unsigned b1=f2tf(Zx[(kc*8+p+4)*40 + nt*8+gr]);
        mma8(&acc[nt*4], a0,a1,a2,a3, b0,b1);
      }
    }
    __syncthreads();
  }
  int q = rb + w*16 + gr;
  #pragma unroll
  for(int nt=0;nt<4;nt++){
    L[ q   *32 + nt*8 + 2*p  ] = acc[nt*4+0];
    L[ q   *32 + nt*8 + 2*p+1] = acc[nt*4+1];
    L[(q+8)*32 + nt*8 + 2*p  ] = acc[nt*4+2];
    L[(q+8)*32 + nt*8 + 2*p+1] = acc[nt*4+3];
  }
}

// ---------------- 2b) reduce partials -> Lambda^T interleaved (unchanged) ----------------
__global__ __launch_bounds__(256) void reduce_kernel(){
  int path = blockIdx.y;
  int idx  = blockIdx.x*256 + threadIdx.x;
  int r = idx>>3, c4 = idx&7;
  float4 s0 = *(const float4*)&g_Lp[path][0][idx*4];
  float4 s1 = *(const float4*)&g_Lp[path][1][idx*4];
  float4 s2 = *(const float4*)&g_Lp[path][2][idx*4];
  float4 s3 = *(const float4*)&g_Lp[path][3][idx*4];
  float vx = s0.x+s1.x+s2.x+s3.x;
  float vy = s0.y+s1.y+s2.y+s3.y;
  float vz = s0.z+s1.z+s2.z+s3.z;
  float vw = s0.w+s1.w+s2.w+s3.w;
  int pos = ilv(r);
  float* LT = path ? g_LTv : g_LTm;
  LT[(c4*4+0)*NROW + pos] = tf2f(vx);
  LT[(c4*4+1)*NROW + pos] = tf2f(vy);
  LT[(c4*4+2)*NROW + pos] = tf2f(vz);
  LT[(c4*4+3)*NROW + pos] = tf2f(vw);
}

// ---------------- 3) fused: bf16 scores -> exp -> tf32 PV (16 warps, M=16/warp) ----------------
template<int D>
__device__ __forceinline__ void fused_body(
    const __nv_bfloat16* __restrict__ Wf, const __nv_bfloat16* __restrict__ XF,
    const float* __restrict__ LTg, const float* __restrict__ QN,
    const float* __restrict__ XN, float* __restrict__ Zout, int qblk){
  extern __shared__ float sm[];
  const int SDh = D + 8;                // bf16 halves; word-stride (D+8)/2 ≡ 4 or 20 mod 32
  __nv_bfloat16* Xs0 = (__nv_bfloat16*)sm;
  __nv_bfloat16* Xs1 = Xs0 + 128*SDh;
  float* LT0 = (float*)(Xs1 + 128*SDh); // Lambda tile, 32 x 136 (fp32)
  float* LT1 = LT0 + 32*136;
  float* xn0 = LT1 + 32*136;
  float* xn1 = xn0 + 128;
  float* Kt  = xn1 + 128;               // 16 warps x (16x40) fp32
  int tid=threadIdx.x, w=tid>>5, lane=tid&31, gr=lane>>2, p=lane&3;
  int half = w>>3, rbase = (w&7)*16;
  float* Kw = Kt + w*(16*40);
  int q0 = qblk*128;
  const int NF8 = 128*(D/8);            // 16B = 8-half chunks per X tile

  // ---- prologue: W tile (bf16) -> A-frags ----
  for(int i=tid;i<NF8;i+=512){
    int r=i/(D/8), c8=i%(D/8);
    cpa16(&Xs0[r*SDh+c8*8], &Wf[(size_t)(q0+r)*D + c8*8]);
  }
  cpa_commit(); cpa_wait0(); __syncthreads();
  unsigned wa[D/16][4];
  #pragma unroll
  for(int kk=0;kk<D/16;kk++){
    wa[kk][0] = *(unsigned*)&Xs0[(rbase+gr  )*SDh + kk*16+2*p  ];
    wa[kk][1] = *(unsigned*)&Xs0[(rbase+gr+8)*SDh + kk*16+2*p  ];
    wa[kk][2] = *(unsigned*)&Xs0[(rbase+gr  )*SDh + kk*16+2*p+8];
    wa[kk][3] = *(unsigned*)&Xs0[(rbase+gr+8)*SDh + kk*16+2*p+8];
  }
  float qn0=QN[q0+rbase+gr], qn1=QN[q0+rbase+gr+8];
  __syncthreads();

  float z[16];
  #pragma unroll
  for(int i=0;i<16;i++) z[i]=0.f;
  const float CL = 1.1271055e-2f;       // log2(e)/128

  auto load_tile = [&](__nv_bfloat16* Xd, float* Ld, float* xd, int xb){
    for(int i=tid;i<NF8;i+=512){
      int r=i/(D/8), c8=i%(D/8);
      cpa16(&Xd[r*SDh+c8*8], &XF[(size_t)(xb+r)*D + c8*8]);
    }
    for(int i=tid;i<1024;i+=512){
      int c=i>>5, ch=i&31;
      cpa16(&Ld[c*136+ch*4], &LTg[(size_t)c*NROW + xb + ch*4]);
    }
    if(tid<32) cpa16(&xd[tid*4], &XN[xb+tid*4]);
  };

  load_tile(Xs0, LT0, xn0, 0); cpa_commit();

  for(int t=0;t<64;t++){
    cpa_wait0(); __syncthreads();
    if(t<63){
      if(t&1) load_tile(Xs0, LT0, xn0, (t+1)*128);
      else    load_tile(Xs1, LT1, xn1, (t+1)*128);
      cpa_commit();
    }
    __nv_bfloat16* X_ = (t&1)? Xs1 : Xs0;
    float* L_  = (t&1)? LT1 : LT0;
    float* xn_ = (t&1)? xn1 : xn0;
    #pragma unroll
    for(int xsi=0; xsi<2; xsi++){
      int xs = half*2 + xsi;
      float s[16];
      #pragma unroll
      for(int i=0;i<16;i++) s[i]=0.f;
      #pragma unroll
      for(int kk=0;kk<D/16;kk++){
        #pragma unroll
        for(int nt=0;nt<4;nt++){
          const __nv_bfloat16* br = &X_[(xs*32+nt*8+gr)*SDh + kk*16+2*p];
          unsigned b0 = *(unsigned*)br;
          unsigned b1 = *(unsigned*)(br+8);
          mma16(&s[nt*4], wa[kk][0],wa[kk][1],wa[kk][2],wa[kk][3], b0,b1);
        }
      }
      int pb = (p<2)? 4*p : 4*p-7;      // interleaved store base for cols 2p,2p+1
      #pragma unroll
      for(int nt=0;nt<4;nt++){
        float xnA=xn_[xs*32+nt*8+2*p], xnB=xn_[xs*32+nt*8+2*p+1];
        Kw[(gr  )*40+nt*8+pb  ]=tf2f(ex2f(fminf(2.f*s[nt*4+0]-qn0-xnA,0.f)*CL));
        Kw[(gr  )*40+nt*8+pb+2]=tf2f(ex2f(fminf(2.f*s[nt*4+1]-qn0-xnB,0.f)*CL));
        Kw[(gr+8)*40+nt*8+pb  ]=tf2f(ex2f(fminf(2.f*s[nt*4+2]-qn1-xnA,0.f)*CL));
        Kw[(gr+8)*40+nt*8+pb+2]=tf2f(ex2f(fminf(2.f*s[nt*4+3]-qn1-xnB,0.f)*CL));
      }
      __syncwarp();
      #pragma unroll
      for(int kc=0;kc<4;kc++){
        float2 Al=*(float2*)&Kw[(gr  )*40+kc*8+2*p];
        float2 Ah=*(float2*)&Kw[(gr+8)*40+kc*8+2*p];
        #pragma unroll
        for(int nt=0;nt<4;nt++){
          float2 b=*(float2*)&L_[(nt*8+gr)*136 + xs*32 + kc*8+2*p];
          mma8(&z[nt*4], fbits(Al.x),fbits(Ah.x),fbits(Al.y),fbits(Ah.y),
               fbits(b.x),fbits(b.y));
        }
      }
      __syncwarp();
    }
  }

  // ---- cross-half z reduction ----
  __syncthreads();
  float* Zr = LT0;                      // reuse
  if(half==0){
    #pragma unroll
    for(int nt=0;nt<4;nt++){
      *(float2*)&Zr[(rbase+gr  )*34 + nt*8+2*p] = make_float2(z[nt*4+0], z[nt*4+1]);
      *(float2*)&Zr[(rbase+gr+8)*34 + nt*8+2*p] = make_float2(z[nt*4+2], z[nt*4+3]);
    }
  }
  __syncthreads();
  if(half==1){
    #pragma unroll
    for(int nt=0;nt<4;nt++){
      float2 a=*(float2*)&Zr[(rbase+gr  )*34 + nt*8+2*p];
      float2 b=*(float2*)&Zr[(rbase+gr+8)*34 + nt*8+2*p];
      *(float2*)&Zout[(size_t)(q0+rbase+gr  )*32 + nt*8+2*p] =
          make_float2(a.x+z[nt*4+0], a.y+z[nt*4+1]);
      *(float2*)&Zout[(size_t)(q0+rbase+gr+8)*32 + nt*8+2*p] =
          make_float2(b.x+z[nt*4+2], b.y+z[nt*4+3]);
    }
  }
}

__global__ __launch_bounds__(512,1) void fused_kernel(){
  if(blockIdx.y==0) fused_body<64>(g_Wm,g_XFm,g_LTm,g_QNm,g_XNm,g_Zm,blockIdx.x);
  else              fused_body<96>(g_Wv,g_XFv,g_LTv,g_QNv,g_XNv,g_Zv,blockIdx.x);
}

// ---------------- 4) finalize ----------------
__global__ __launch_bounds__(256) void final_kernel(
    const float* __restrict__ y_mean, const float* __restrict__ y_var,
    float* __restrict__ out){
  int i = blockIdx.x*256 + threadIdx.x;
  float4 a=*(const float4*)&y_mean[i*4];
  float4 b=*(const float4*)&y_var [i*4];
  float4 zm=*(const float4*)&g_Zm[i*4];
  float4 zv=*(const float4*)&g_Zv[i*4];
  float4 o;
  o.x=a.x+b.x+zm.x+zv.x; o.y=a.y+b.y+zm.y+zv.y;
  o.z=a.z+b.z+zm.z+zv.z; o.w=a.w+b.w+zm.w+zv.w;
  *(float4*)&out[i*4]=o;
}

extern "C" void kernel_launch(void* const* d_in, const int* in_sizes, int n_in,
                              void* d_out, int out_size){
  const float* x_mu   = (const float*)d_in[0];
  const float* y_eta  = (const float*)d_in[1];
  const float* y_mean = (const float*)d_in[2];
  const float* y_var  = (const float*)d_in[3];
  const float* X_mean = (const float*)d_in[4];
  const float* X_var  = (const float*)d_in[5];
  const float* Z_mean = (const float*)d_in[6];
  const float* Z_var  = (const float*)d_in[7];
  const float* kMinv  = (const float*)d_in[8];
  const float* kVinv  = (const float*)d_in[9];
  float* out = (float*)d_out;

  prep_kernel<<<NROW/8, 256>>>(x_mu, y_eta, y_mean, y_var, X_mean, X_var);
  lambda_kernel<<<dim3(NROW/64,4,2), 128>>>(kMinv, kVinv, Z_mean, Z_var);
  reduce_kernel<<<dim3(256,2), 256>>>();
  // smem (D=96): X bf16 2*128*104*2 = 53248 B; LT 2*32*136*4 = 34816 B;
  // xn 2*128*4 = 1024 B; Kw 16*16*40*4 = 40960 B  => 130048 B
  const int FSM = 2*128*104*2 + 2*32*136*4 + 2*128*4 + 16*16*40*4;
  cudaFuncSetAttribute(fused_kernel, cudaFuncAttributeMaxDynamicSharedMemorySize, FSM);
  fused_kernel<<<dim3(64,2), 512, FSM>>>();
  final_kernel<<<NROW*32/4/256, 256>>>(y_mean, y_var, out);
}

// round 13
// speedup vs baseline: 1.4216x; 1.1943x over previous
#include <cuda_runtime.h>
#include <cuda_bf16.h>
#include <cuda_fp16.h>
#include <cstdint>

#define NROW 8192

// ---------------- scratch ----------------
__device__ __nv_bfloat16 g_Wm [NROW*64];   // plain row-major bf16
__device__ __nv_bfloat16 g_Wv [NROW*96];
__device__ __nv_bfloat16 g_XFm[NROW*64];
__device__ __nv_bfloat16 g_XFv[NROW*96];
__device__ float  g_Lp [2][4][NROW*32];    // lambda partials (fp32)
__device__ __half g_LTm[32*NROW];          // Lambda^T plain fp16
__device__ __half g_LTv[32*NROW];
__device__ float g_QNm[NROW];
__device__ float g_QNv[NROW];
__device__ float g_XNm[NROW];
__device__ float g_XNv[NROW];
__device__ float g_Zm [NROW*32];
__device__ float g_Zv [NROW*32];

__device__ __forceinline__ unsigned f2tf(float x){
  unsigned r; asm("cvt.rna.tf32.f32 %0, %1;" : "=r"(r) : "f"(x)); return r;
}
__device__ __forceinline__ float ex2f(float x){
  float r; asm("ex2.approx.f32 %0, %1;" : "=f"(r) : "f"(x)); return r;
}
// tf32 k8 mma (lambda only)
__device__ __forceinline__ void mma8(float* c, unsigned a0,unsigned a1,unsigned a2,unsigned a3,
                                     unsigned b0,unsigned b1){
  asm volatile("mma.sync.aligned.m16n8k8.row.col.f32.tf32.tf32.f32 "
               "{%0,%1,%2,%3},{%4,%5,%6,%7},{%8,%9},{%0,%1,%2,%3};\n"
               : "+f"(c[0]), "+f"(c[1]), "+f"(c[2]), "+f"(c[3])
               : "r"(a0), "r"(a1), "r"(a2), "r"(a3), "r"(b0), "r"(b1));
}
// bf16 k16 mma (score)
__device__ __forceinline__ void mma16b(float* c, unsigned a0,unsigned a1,unsigned a2,unsigned a3,
                                       unsigned b0,unsigned b1){
  asm volatile("mma.sync.aligned.m16n8k16.row.col.f32.bf16.bf16.f32 "
               "{%0,%1,%2,%3},{%4,%5,%6,%7},{%8,%9},{%0,%1,%2,%3};\n"
               : "+f"(c[0]), "+f"(c[1]), "+f"(c[2]), "+f"(c[3])
               : "r"(a0), "r"(a1), "r"(a2), "r"(a3), "r"(b0), "r"(b1));
}
// fp16 k16 mma (PV)
__device__ __forceinline__ void mma16h(float* c, unsigned a0,unsigned a1,unsigned a2,unsigned a3,
                                       unsigned b0,unsigned b1){
  asm volatile("mma.sync.aligned.m16n8k16.row.col.f32.f16.f16.f32 "
               "{%0,%1,%2,%3},{%4,%5,%6,%7},{%8,%9},{%0,%1,%2,%3};\n"
               : "+f"(c[0]), "+f"(c[1]), "+f"(c[2]), "+f"(c[3])
               : "r"(a0), "r"(a1), "r"(a2), "r"(a3), "r"(b0), "r"(b1));
}
__device__ __forceinline__ void cpa16(void* dst, const void* src){
  unsigned d = (unsigned)__cvta_generic_to_shared(dst);
  asm volatile("cp.async.cg.shared.global [%0], [%1], 16;\n" :: "r"(d), "l"(src));
}
__device__ __forceinline__ void cpa_commit(){ asm volatile("cp.async.commit_group;\n"); }
__device__ __forceinline__ void cpa_wait0(){ asm volatile("cp.async.wait_group 0;\n"); }
__device__ __forceinline__ void cpa_wait1(){ asm volatile("cp.async.wait_group 1;\n"); }

// ---------------- 1) prep ----------------
__global__ __launch_bounds__(256) void prep_kernel(
    const float* __restrict__ x_mu, const float* __restrict__ y_eta,
    const float* __restrict__ y_mean, const float* __restrict__ y_var,
    const float* __restrict__ X_mean, const float* __restrict__ X_var){
  int row  = blockIdx.x*8 + (threadIdx.x>>5);
  int lane = threadIdx.x & 31;
  float xm = x_mu [row*32+lane];
  float s  = y_mean[row*32+lane] + y_var[row*32+lane];
  float fe = 0.01f * y_eta[(NROW-1-row)*32+lane];
  g_Wm[row*64+lane]    = __float2bfloat16_rn(xm);
  g_Wm[row*64+32+lane] = __float2bfloat16_rn(s);
  g_Wv[row*96+lane]    = __float2bfloat16_rn(xm);
  g_Wv[row*96+32+lane] = __float2bfloat16_rn(fe);
  g_Wv[row*96+64+lane] = __float2bfloat16_rn(s);
  float qm = xm*xm + s*s;
  float qv = qm + fe*fe;
  float a  = X_mean[row*64+lane], bm = X_mean[row*64+32+lane];
  g_XFm[row*64+lane]    = __float2bfloat16_rn(a);
  g_XFm[row*64+32+lane] = __float2bfloat16_rn(bm);
  float nm = a*a + bm*bm;
  float c0 = X_var[row*96+lane], c1 = X_var[row*96+32+lane], c2 = X_var[row*96+64+lane];
  g_XFv[row*96+lane]    = __float2bfloat16_rn(c0);
  g_XFv[row*96+32+lane] = __float2bfloat16_rn(c1);
  g_XFv[row*96+64+lane] = __float2bfloat16_rn(c2);
  float nv = c0*c0 + c1*c1 + c2*c2;
  #pragma unroll
  for(int o=16;o;o>>=1){
    qm += __shfl_xor_sync(0xffffffffu,qm,o);
    qv += __shfl_xor_sync(0xffffffffu,qv,o);
    nm += __shfl_xor_sync(0xffffffffu,nm,o);
    nv += __shfl_xor_sync(0xffffffffu,nv,o);
  }
  if(lane==0){ g_QNm[row]=qm; g_QNv[row]=qv; g_XNm[row]=nm; g_XNv[row]=nv; }
}

// ---------------- 2) Lambda partials (tf32, unchanged) ----------------
__global__ __launch_bounds__(128) void lambda_kernel(
    const float* __restrict__ Am, const float* __restrict__ Av,
    const float* __restrict__ Zm, const float* __restrict__ Zv){
  int path = blockIdx.z, ks = blockIdx.y;
  const float* A = path ? Av : Am;
  const float* Z = path ? Zv : Zm;
  float* L = &g_Lp[path][ks][0];
  __shared__ float As[2][64*36];
  __shared__ float Zs[2][32*40];
  int tid=threadIdx.x, w=tid>>5, lane=tid&31, gr=lane>>2, p=lane&3;
  int rb = blockIdx.x*64, kbase = ks*2048;

  auto load = [&](int st, int k0){
    #pragma unroll
    for(int i=0;i<4;i++){
      int idx=tid+128*i; int r=idx>>3, c4=idx&7;
      cpa16(&As[st][r*36+c4*4], &A[(size_t)(rb+r)*NROW + k0 + c4*4]);
    }
    #pragma unroll
    for(int i=0;i<2;i++){
      int idx=tid+128*i; int r=idx>>3, c4=idx&7;
      cpa16(&Zs[st][r*40+c4*4], &Z[(size_t)(k0+r)*32 + c4*4]);
    }
  };

  load(0, kbase); cpa_commit();
  float acc[16];
  #pragma unroll
  for(int i=0;i<16;i++) acc[i]=0.f;

  for(int kt=0;kt<64;kt++){
    if(kt<63){ load((kt+1)&1, kbase+(kt+1)*32); cpa_commit(); cpa_wait1(); }
    else cpa_wait0();
    __syncthreads();
    const float* Ax = As[kt&1];
    const float* Zx = Zs[kt&1];
    #pragma unroll
    for(int kc=0;kc<4;kc++){
      unsigned a0=f2tf(Ax[(w*16+gr  )*36 + kc*8+p  ]);
      unsigned a1=f2tf(Ax[(w*16+gr+8)*36 + kc*8+p  ]);
      unsigned a2=f2tf(Ax[(w*16+gr  )*36 + kc*8+p+4]);
      unsigned a3=f2tf(Ax[(w*16+gr+8)*36 + kc*8+p+4]);
      #pragma unroll
      for(int nt=0;nt<4;nt++){
        unsigned b0=f2tf(Zx[(kc*8+p  )*40 + nt*8+gr]);
        unsigned b1=f2tf(Zx[(kc*8+p+4)*40 + nt*8+gr]);
        mma8(&acc[nt*4], a0,a1,a2,a3, b0,b1);
      }
    }
    __syncthreads();
  }
  int q = rb + w*16 + gr;
  #pragma unroll
  for(int nt=0;nt<4;nt++){
    L[ q   *32 + nt*8 + 2*p  ] = acc[nt*4+0];
    L[ q   *32 + nt*8 + 2*p+1] = acc[nt*4+1];
    L[(q+8)*32 + nt*8 + 2*p  ] = acc[nt*4+2];
    L[(q+8)*32 + nt*8 + 2*p+1] = acc[nt*4+3];
  }
}

// ---------------- 2b) reduce partials -> Lambda^T plain fp16 ----------------
__global__ __launch_bounds__(256) void reduce_kernel(){
  int path = blockIdx.y;
  int idx  = blockIdx.x*256 + threadIdx.x;
  int r = idx>>3, c4 = idx&7;
  float4 s0 = *(const float4*)&g_Lp[path][0][idx*4];
  float4 s1 = *(const float4*)&g_Lp[path][1][idx*4];
  float4 s2 = *(const float4*)&g_Lp[path][2][idx*4];
  float4 s3 = *(const float4*)&g_Lp[path][3][idx*4];
  __half* LT = path ? g_LTv : g_LTm;
  LT[(c4*4+0)*NROW + r] = __float2half_rn(s0.x+s1.x+s2.x+s3.x);
  LT[(c4*4+1)*NROW + r] = __float2half_rn(s0.y+s1.y+s2.y+s3.y);
  LT[(c4*4+2)*NROW + r] = __float2half_rn(s0.z+s1.z+s2.z+s3.z);
  LT[(c4*4+3)*NROW + r] = __float2half_rn(s0.w+s1.w+s2.w+s3.w);
}

// ---------------- 3) fused: bf16 scores -> exp -> fp16 PV ----------------
template<int D>
__device__ __forceinline__ void fused_body(
    const __nv_bfloat16* __restrict__ Wf, const __nv_bfloat16* __restrict__ XF,
    const __half* __restrict__ LTg, const float* __restrict__ QN,
    const float* __restrict__ XN, float* __restrict__ Zout, int qblk){
  extern __shared__ float sm[];
  const int SDh = D + 8;                // bf16 halves per X row
  const int SDL = 136;                  // fp16 halves per Lambda row
  __nv_bfloat16* Xs0 = (__nv_bfloat16*)sm;
  __nv_bfloat16* Xs1 = Xs0 + 128*SDh;
  __half* LT0 = (__half*)(Xs1 + 128*SDh);   // 32 x 136 fp16
  __half* LT1 = LT0 + 32*SDL;
  float* xn0 = (float*)(LT1 + 32*SDL);
  float* xn1 = xn0 + 128;
  __half* Kt = (__half*)(xn1 + 128);    // 16 warps x (16x40) fp16
  int tid=threadIdx.x, w=tid>>5, lane=tid&31, gr=lane>>2, p=lane&3;
  int half_ = w>>3, rbase = (w&7)*16;
  __half* Kw = Kt + w*(16*40);
  int q0 = qblk*128;
  const int NF8 = 128*(D/8);

  // ---- prologue: W tile (bf16) -> A-frags ----
  for(int i=tid;i<NF8;i+=512){
    int r=i/(D/8), c8=i%(D/8);
    cpa16(&Xs0[r*SDh+c8*8], &Wf[(size_t)(q0+r)*D + c8*8]);
  }
  cpa_commit(); cpa_wait0(); __syncthreads();
  unsigned wa[D/16][4];
  #pragma unroll
  for(int kk=0;kk<D/16;kk++){
    wa[kk][0] = *(unsigned*)&Xs0[(rbase+gr  )*SDh + kk*16+2*p  ];
    wa[kk][1] = *(unsigned*)&Xs0[(rbase+gr+8)*SDh + kk*16+2*p  ];
    wa[kk][2] = *(unsigned*)&Xs0[(rbase+gr  )*SDh + kk*16+2*p+8];
    wa[kk][3] = *(unsigned*)&Xs0[(rbase+gr+8)*SDh + kk*16+2*p+8];
  }
  float qn0=QN[q0+rbase+gr], qn1=QN[q0+rbase+gr+8];
  __syncthreads();

  float z[16];
  #pragma unroll
  for(int i=0;i<16;i++) z[i]=0.f;
  const float CL = 1.1271055e-2f;       // log2(e)/128

  auto load_tile = [&](__nv_bfloat16* Xd, __half* Ld, float* xd, int xb){
    for(int i=tid;i<NF8;i+=512){
      int r=i/(D/8), c8=i%(D/8);
      cpa16(&Xd[r*SDh+c8*8], &XF[(size_t)(xb+r)*D + c8*8]);
    }
    {
      int c=tid>>4, ch=tid&15;          // 512 threads cover 32 x 16 chunks
      cpa16(&Ld[c*SDL+ch*8], &LTg[(size_t)c*NROW + xb + ch*8]);
    }
    if(tid<32) cpa16(&xd[tid*4], &XN[xb+tid*4]);
  };

  load_tile(Xs0, LT0, xn0, 0); cpa_commit();

  for(int t=0;t<64;t++){
    cpa_wait0(); __syncthreads();
    if(t<63){
      if(t&1) load_tile(Xs0, LT0, xn0, (t+1)*128);
      else    load_tile(Xs1, LT1, xn1, (t+1)*128);
      cpa_commit();
    }
    __nv_bfloat16* X_ = (t&1)? Xs1 : Xs0;
    __half* L_ = (t&1)? LT1 : LT0;
    float* xn_ = (t&1)? xn1 : xn0;
    #pragma unroll
    for(int xsi=0; xsi<2; xsi++){
      int xs = half_*2 + xsi;
      float s[16];
      #pragma unroll
      for(int i=0;i<16;i++) s[i]=0.f;
      #pragma unroll
      for(int kk=0;kk<D/16;kk++){
        #pragma unroll
        for(int nt=0;nt<4;nt++){
          const __nv_bfloat16* br = &X_[(xs*32+nt*8+gr)*SDh + kk*16+2*p];
          unsigned b0 = *(unsigned*)br;
          unsigned b1 = *(unsigned*)(br+8);
          mma16b(&s[nt*4], wa[kk][0],wa[kk][1],wa[kk][2],wa[kk][3], b0,b1);
        }
      }
      // epilogue: K = exp2(min(2S - qn - xn, 0)*CL), staged to Kw as fp16 pairs
      #pragma unroll
      for(int nt=0;nt<4;nt++){
        float xnA=xn_[xs*32+nt*8+2*p], xnB=xn_[xs*32+nt*8+2*p+1];
        float k0=ex2f(fminf(2.f*s[nt*4+0]-qn0-xnA,0.f)*CL);
        float k1=ex2f(fminf(2.f*s[nt*4+1]-qn0-xnB,0.f)*CL);
        float k2=ex2f(fminf(2.f*s[nt*4+2]-qn1-xnA,0.f)*CL);
        float k3=ex2f(fminf(2.f*s[nt*4+3]-qn1-xnB,0.f)*CL);
        *(__half2*)&Kw[(gr  )*40 + nt*8+2*p] = __floats2half2_rn(k0,k1);
        *(__half2*)&Kw[(gr+8)*40 + nt*8+2*p] = __floats2half2_rn(k2,k3);
      }
      __syncwarp();
      // PV: z += K(16 x 32) * Lambda(32 x 32), fp16 k16 x2
      #pragma unroll
      for(int kc=0;kc<2;kc++){
        unsigned a0 = *(unsigned*)&Kw[(gr  )*40 + kc*16+2*p  ];
        unsigned a1 = *(unsigned*)&Kw[(gr+8)*40 + kc*16+2*p  ];
        unsigned a2 = *(unsigned*)&Kw[(gr  )*40 + kc*16+2*p+8];
        unsigned a3 = *(unsigned*)&Kw[(gr+8)*40 + kc*16+2*p+8];
        #pragma unroll
        for(int nt=0;nt<4;nt++){
          const __half* lr = &L_[(nt*8+gr)*SDL + xs*32 + kc*16+2*p];
          unsigned b0 = *(unsigned*)lr;
          unsigned b1 = *(unsigned*)(lr+8);
          mma16h(&z[nt*4], a0,a1,a2,a3, b0,b1);
        }
      }
      __syncwarp();
    }
  }

  // ---- cross-half z reduction (reuse Kt as fp32 scratch: 20480B >= 17408B) ----
  __syncthreads();
  float* Zr = (float*)Kt;
  if(half_==0){
    #pragma unroll
    for(int nt=0;nt<4;nt++){
      *(float2*)&Zr[(rbase+gr  )*34 + nt*8+2*p] = make_float2(z[nt*4+0], z[nt*4+1]);
      *(float2*)&Zr[(rbase+gr+8)*34 + nt*8+2*p] = make_float2(z[nt*4+2], z[nt*4+3]);
    }
  }
  __syncthreads();
  if(half_==1){
    #pragma unroll
    for(int nt=0;nt<4;nt++){
      float2 a=*(float2*)&Zr[(rbase+gr  )*34 + nt*8+2*p];
      float2 b=*(float2*)&Zr[(rbase+gr+8)*34 + nt*8+2*p];
      *(float2*)&Zout[(size_t)(q0+rbase+gr  )*32 + nt*8+2*p] =
          make_float2(a.x+z[nt*4+0], a.y+z[nt*4+1]);
      *(float2*)&Zout[(size_t)(q0+rbase+gr+8)*32 + nt*8+2*p] =
          make_float2(b.x+z[nt*4+2], b.y+z[nt*4+3]);
    }
  }
}

__global__ __launch_bounds__(512,1) void fused_kernel(){
  if(blockIdx.y==0) fused_body<64>(g_Wm,g_XFm,g_LTm,g_QNm,g_XNm,g_Zm,blockIdx.x);
  else              fused_body<96>(g_Wv,g_XFv,g_LTv,g_QNv,g_XNv,g_Zv,blockIdx.x);
}

// ---------------- 4) finalize ----------------
__global__ __launch_bounds__(256) void final_kernel(
    const float* __restrict__ y_mean, const float* __restrict__ y_var,
    float* __restrict__ out){
  int i = blockIdx.x*256 + threadIdx.x;
  float4 a=*(const float4*)&y_mean[i*4];
  float4 b=*(const float4*)&y_var [i*4];
  float4 zm=*(const float4*)&g_Zm[i*4];
  float4 zv=*(const float4*)&g_Zv[i*4];
  float4 o;
  o.x=a.x+b.x+zm.x+zv.x; o.y=a.y+b.y+zm.y+zv.y;
  o.z=a.z+b.z+zm.z+zv.z; o.w=a.w+b.w+zm.w+zv.w;
  *(float4*)&out[i*4]=o;
}

extern "C" void kernel_launch(void* const* d_in, const int* in_sizes, int n_in,
                              void* d_out, int out_size){
  const float* x_mu   = (const float*)d_in[0];
  const float* y_eta  = (const float*)d_in[1];
  const float* y_mean = (const float*)d_in[2];
  const float* y_var  = (const float*)d_in[3];
  const float* X_mean = (const float*)d_in[4];
  const float* X_var  = (const float*)d_in[5];
  const float* Z_mean = (const float*)d_in[6];
  const float* Z_var  = (const float*)d_in[7];
  const float* kMinv  = (const float*)d_in[8];
  const float* kVinv  = (const float*)d_in[9];
  float* out = (float*)d_out;

  prep_kernel<<<NROW/8, 256>>>(x_mu, y_eta, y_mean, y_var, X_mean, X_var);
  lambda_kernel<<<dim3(NROW/64,4,2), 128>>>(kMinv, kVinv, Z_mean, Z_var);
  reduce_kernel<<<dim3(256,2), 256>>>();
  // smem (D=96): X bf16 2*128*104*2 = 53248; LT fp16 2*32*136*2 = 17408;
  // xn 2*128*4 = 1024; Kw fp16 16*16*40*2 = 20480  => 92160 B
  const int FSM = 2*128*104*2 + 2*32*136*2 + 2*128*4 + 16*16*40*2;
  cudaFuncSetAttribute(fused_kernel, cudaFuncAttributeMaxDynamicSharedMemorySize, FSM);
  fused_kernel<<<dim3(64,2), 512, FSM>>>();
  final_kernel<<<NROW*32/4/256, 256>>>(y_mean, y_var, out);
}

// round 14
// speedup vs baseline: 1.5474x; 1.0885x over previous
#include <cuda_runtime.h>
#include <cuda_bf16.h>
#include <cuda_fp16.h>
#include <cstdint>

#define NROW 8192

// ---------------- scratch ----------------
__device__ __nv_bfloat16 g_Wm [NROW*64];   // row-major bf16, scaled by sqrt(2*CL)
__device__ __nv_bfloat16 g_Wv [NROW*96];
__device__ __nv_bfloat16 g_XFm[NROW*64];
__device__ __nv_bfloat16 g_XFv[NROW*96];
__device__ float  g_Lp [2][4][NROW*32];    // lambda partials (fp32)
__device__ __half g_LTm[32*NROW];          // Lambda^T plain fp16
__device__ __half g_LTv[32*NROW];
__device__ float  g_QNm[NROW];             // CL * |w|^2  (fp32)
__device__ float  g_QNv[NROW];
__device__ __half g_XNm[NROW];             // CL * |x|^2  (fp16)
__device__ __half g_XNv[NROW];
__device__ float g_Zm [NROW*32];
__device__ float g_Zv [NROW*32];

#define CLF 1.1271055e-2f     // log2(e)/128
#define SCF 0.15014030f       // sqrt(2*CLF)

__device__ __forceinline__ unsigned f2tf(float x){
  unsigned r; asm("cvt.rna.tf32.f32 %0, %1;" : "=r"(r) : "f"(x)); return r;
}
// tf32 k8 mma (lambda only)
__device__ __forceinline__ void mma8(float* c, unsigned a0,unsigned a1,unsigned a2,unsigned a3,
                                     unsigned b0,unsigned b1){
  asm volatile("mma.sync.aligned.m16n8k8.row.col.f32.tf32.tf32.f32 "
               "{%0,%1,%2,%3},{%4,%5,%6,%7},{%8,%9},{%0,%1,%2,%3};\n"
               : "+f"(c[0]), "+f"(c[1]), "+f"(c[2]), "+f"(c[3])
               : "r"(a0), "r"(a1), "r"(a2), "r"(a3), "r"(b0), "r"(b1));
}
// bf16 k16 mma (score)
__device__ __forceinline__ void mma16b(float* c, unsigned a0,unsigned a1,unsigned a2,unsigned a3,
                                       unsigned b0,unsigned b1){
  asm volatile("mma.sync.aligned.m16n8k16.row.col.f32.bf16.bf16.f32 "
               "{%0,%1,%2,%3},{%4,%5,%6,%7},{%8,%9},{%0,%1,%2,%3};\n"
               : "+f"(c[0]), "+f"(c[1]), "+f"(c[2]), "+f"(c[3])
               : "r"(a0), "r"(a1), "r"(a2), "r"(a3), "r"(b0), "r"(b1));
}
// fp16 k16 mma (PV)
__device__ __forceinline__ void mma16h(float* c, unsigned a0,unsigned a1,unsigned a2,unsigned a3,
                                       unsigned b0,unsigned b1){
  asm volatile("mma.sync.aligned.m16n8k16.row.col.f32.f16.f16.f32 "
               "{%0,%1,%2,%3},{%4,%5,%6,%7},{%8,%9},{%0,%1,%2,%3};\n"
               : "+f"(c[0]), "+f"(c[1]), "+f"(c[2]), "+f"(c[3])
               : "r"(a0), "r"(a1), "r"(a2), "r"(a3), "r"(b0), "r"(b1));
}
__device__ __forceinline__ void ldsm4(unsigned* r, unsigned addr){
  asm volatile("ldmatrix.sync.aligned.m8n8.x4.shared.b16 {%0,%1,%2,%3}, [%4];"
    : "=r"(r[0]),"=r"(r[1]),"=r"(r[2]),"=r"(r[3]) : "r"(addr));
}
__device__ __forceinline__ void cpa16(void* dst, const void* src){
  unsigned d = (unsigned)__cvta_generic_to_shared(dst);
  asm volatile("cp.async.cg.shared.global [%0], [%1], 16;\n" :: "r"(d), "l"(src));
}
__device__ __forceinline__ void cpa_commit(){ asm volatile("cp.async.commit_group;\n"); }
__device__ __forceinline__ void cpa_wait0(){ asm volatile("cp.async.wait_group 0;\n"); }
__device__ __forceinline__ void cpa_wait1(){ asm volatile("cp.async.wait_group 1;\n"); }

// ---------------- 1) prep ----------------
__global__ __launch_bounds__(256) void prep_kernel(
    const float* __restrict__ x_mu, const float* __restrict__ y_eta,
    const float* __restrict__ y_mean, const float* __restrict__ y_var,
    const float* __restrict__ X_mean, const float* __restrict__ X_var){
  int row  = blockIdx.x*8 + (threadIdx.x>>5);
  int lane = threadIdx.x & 31;
  float xm = x_mu [row*32+lane];
  float s  = y_mean[row*32+lane] + y_var[row*32+lane];
  float fe = 0.01f * y_eta[(NROW-1-row)*32+lane];
  g_Wm[row*64+lane]    = __float2bfloat16_rn(xm*SCF);
  g_Wm[row*64+32+lane] = __float2bfloat16_rn(s*SCF);
  g_Wv[row*96+lane]    = __float2bfloat16_rn(xm*SCF);
  g_Wv[row*96+32+lane] = __float2bfloat16_rn(fe*SCF);
  g_Wv[row*96+64+lane] = __float2bfloat16_rn(s*SCF);
  float qm = xm*xm + s*s;
  float qv = qm + fe*fe;
  float a  = X_mean[row*64+lane], bm = X_mean[row*64+32+lane];
  g_XFm[row*64+lane]    = __float2bfloat16_rn(a*SCF);
  g_XFm[row*64+32+lane] = __float2bfloat16_rn(bm*SCF);
  float nm = a*a + bm*bm;
  float c0 = X_var[row*96+lane], c1 = X_var[row*96+32+lane], c2 = X_var[row*96+64+lane];
  g_XFv[row*96+lane]    = __float2bfloat16_rn(c0*SCF);
  g_XFv[row*96+32+lane] = __float2bfloat16_rn(c1*SCF);
  g_XFv[row*96+64+lane] = __float2bfloat16_rn(c2*SCF);
  float nv = c0*c0 + c1*c1 + c2*c2;
  #pragma unroll
  for(int o=16;o;o>>=1){
    qm += __shfl_xor_sync(0xffffffffu,qm,o);
    qv += __shfl_xor_sync(0xffffffffu,qv,o);
    nm += __shfl_xor_sync(0xffffffffu,nm,o);
    nv += __shfl_xor_sync(0xffffffffu,nv,o);
  }
  if(lane==0){
    g_QNm[row]=qm*CLF; g_QNv[row]=qv*CLF;
    g_XNm[row]=__float2half_rn(nm*CLF); g_XNv[row]=__float2half_rn(nv*CLF);
  }
}

// ---------------- 2) Lambda partials (tf32, unchanged) ----------------
__global__ __launch_bounds__(128) void lambda_kernel(
    const float* __restrict__ Am, const float* __restrict__ Av,
    const float* __restrict__ Zm, const float* __restrict__ Zv){
  int path = blockIdx.z, ks = blockIdx.y;
  const float* A = path ? Av : Am;
  const float* Z = path ? Zv : Zm;
  float* L = &g_Lp[path][ks][0];
  __shared__ float As[2][64*36];
  __shared__ float Zs[2][32*40];
  int tid=threadIdx.x, w=tid>>5, lane=tid&31, gr=lane>>2, p=lane&3;
  int rb = blockIdx.x*64, kbase = ks*2048;

  auto load = [&](int st, int k0){
    #pragma unroll
    for(int i=0;i<4;i++){
      int idx=tid+128*i; int r=idx>>3, c4=idx&7;
      cpa16(&As[st][r*36+c4*4], &A[(size_t)(rb+r)*NROW + k0 + c4*4]);
    }
    #pragma unroll
    for(int i=0;i<2;i++){
      int idx=tid+128*i; int r=idx>>3, c4=idx&7;
      cpa16(&Zs[st][r*40+c4*4], &Z[(size_t)(k0+r)*32 + c4*4]);
    }
  };

  load(0, kbase); cpa_commit();
  float acc[16];
  #pragma unroll
  for(int i=0;i<16;i++) acc[i]=0.f;

  for(int kt=0;kt<64;kt++){
    if(kt<63){ load((kt+1)&1, kbase+(kt+1)*32); cpa_commit(); cpa_wait1(); }
    else cpa_wait0();
    __syncthreads();
    const float* Ax = As[kt&1];
    const float* Zx = Zs[kt&1];
    #pragma unroll
    for(int kc=0;kc<4;kc++){
      unsigned a0=f2tf(Ax[(w*16+gr  )*36 + kc*8+p  ]);
      unsigned a1=f2tf(Ax[(w*16+gr+8)*36 + kc*8+p  ]);
      unsigned a2=f2tf(Ax[(w*16+gr  )*36 + kc*8+p+4]);
      unsigned a3=f2tf(Ax[(w*16+gr+8)*36 + kc*8+p+4]);
      #pragma unroll
      for(int nt=0;nt<4;nt++){
        unsigned b0=f2tf(Zx[(kc*8+p  )*40 + nt*8+gr]);
        unsigned b1=f2tf(Zx[(kc*8+p+4)*40 + nt*8+gr]);
        mma8(&acc[nt*4], a0,a1,a2,a3, b0,b1);
      }
    }
    __syncthreads();
  }
  int q = rb + w*16 + gr;
  #pragma unroll
  for(int nt=0;nt<4;nt++){
    L[ q   *32 + nt*8 + 2*p  ] = acc[nt*4+0];
    L[ q   *32 + nt*8 + 2*p+1] = acc[nt*4+1];
    L[(q+8)*32 + nt*8 + 2*p  ] = acc[nt*4+2];
    L[(q+8)*32 + nt*8 + 2*p+1] = acc[nt*4+3];
  }
}

// ---------------- 2b) reduce partials -> Lambda^T plain fp16 ----------------
__global__ __launch_bounds__(256) void reduce_kernel(){
  int path = blockIdx.y;
  int idx  = blockIdx.x*256 + threadIdx.x;
  int r = idx>>3, c4 = idx&7;
  float4 s0 = *(const float4*)&g_Lp[path][0][idx*4];
  float4 s1 = *(const float4*)&g_Lp[path][1][idx*4];
  float4 s2 = *(const float4*)&g_Lp[path][2][idx*4];
  float4 s3 = *(const float4*)&g_Lp[path][3][idx*4];
  __half* LT = path ? g_LTv : g_LTm;
  LT[(c4*4+0)*NROW + r] = __float2half_rn(s0.x+s1.x+s2.x+s3.x);
  LT[(c4*4+1)*NROW + r] = __float2half_rn(s0.y+s1.y+s2.y+s3.y);
  LT[(c4*4+2)*NROW + r] = __float2half_rn(s0.z+s1.z+s2.z+s3.z);
  LT[(c4*4+3)*NROW + r] = __float2half_rn(s0.w+s1.w+s2.w+s3.w);
}

// ---------------- 3) fused: bf16 scores -> f16x2 exp -> fp16 PV, register-resident K ----------------
template<int D>
__device__ __forceinline__ void fused_body(
    const __nv_bfloat16* __restrict__ Wf, const __nv_bfloat16* __restrict__ XF,
    const __half* __restrict__ LTg, const float* __restrict__ QN,
    const __half* __restrict__ XNh, float* __restrict__ Zout, int qblk){
  extern __shared__ float sm[];
  const int SDh = D + 8;                // bf16 halves per X row
  const int SDL = 136;                  // fp16 halves per Lambda row
  __nv_bfloat16* Xs0 = (__nv_bfloat16*)sm;
  __nv_bfloat16* Xs1 = Xs0 + 128*SDh;
  __half* LT0 = (__half*)(Xs1 + 128*SDh);   // 32 x 136 fp16
  __half* LT1 = LT0 + 32*SDL;
  __half* xn0 = LT1 + 32*SDL;
  __half* xn1 = xn0 + 128;
  int tid=threadIdx.x, w=tid>>5, lane=tid&31, gr=lane>>2, p=lane&3;
  int half_ = w>>3, rbase = (w&7)*16;
  int q0 = qblk*128;
  const int NF8 = 128*(D/8);

  // ---- prologue: W tile (bf16) -> A-frags ----
  for(int i=tid;i<NF8;i+=512){
    int r=i/(D/8), c8=i%(D/8);
    cpa16(&Xs0[r*SDh+c8*8], &Wf[(size_t)(q0+r)*D + c8*8]);
  }
  cpa_commit(); cpa_wait0(); __syncthreads();
  unsigned wa[D/16][4];
  #pragma unroll
  for(int kk=0;kk<D/16;kk++){
    wa[kk][0] = *(unsigned*)&Xs0[(rbase+gr  )*SDh + kk*16+2*p  ];
    wa[kk][1] = *(unsigned*)&Xs0[(rbase+gr+8)*SDh + kk*16+2*p  ];
    wa[kk][2] = *(unsigned*)&Xs0[(rbase+gr  )*SDh + kk*16+2*p+8];
    wa[kk][3] = *(unsigned*)&Xs0[(rbase+gr+8)*SDh + kk*16+2*p+8];
  }
  float qn0c=QN[q0+rbase+gr], qn1c=QN[q0+rbase+gr+8];
  __syncthreads();

  float z[16];
  #pragma unroll
  for(int i=0;i<16;i++) z[i]=0.f;

  auto load_tile = [&](__nv_bfloat16* Xd, __half* Ld, __half* xd, int xb){
    for(int i=tid;i<NF8;i+=512){
      int r=i/(D/8), c8=i%(D/8);
      cpa16(&Xd[r*SDh+c8*8], &XF[(size_t)(xb+r)*D + c8*8]);
    }
    {
      int c=tid>>4, ch=tid&15;          // 512 threads cover 32 x 16 chunks
      cpa16(&Ld[c*SDL+ch*8], &LTg[(size_t)c*NROW + xb + ch*8]);
    }
    if(tid<16) cpa16(&xd[tid*8], &XNh[xb+tid*8]);
  };

  load_tile(Xs0, LT0, xn0, 0); cpa_commit();
  const __half2 zero2 = __float2half2_rn(0.f);

  for(int t=0;t<64;t++){
    cpa_wait0(); __syncthreads();
    if(t<63){
      if(t&1) load_tile(Xs0, LT0, xn0, (t+1)*128);
      else    load_tile(Xs1, LT1, xn1, (t+1)*128);
      cpa_commit();
    }
    __nv_bfloat16* X_ = (t&1)? Xs1 : Xs0;
    __half* L_ = (t&1)? LT1 : LT0;
    __half* xn_ = (t&1)? xn1 : xn0;
    #pragma unroll
    for(int xsi=0; xsi<2; xsi++){
      int xs = half_*2 + xsi;
      float s[16];
      #pragma unroll
      for(int i=0;i<16;i++) s[i]=0.f;
      // score: ldmatrix B-frags (tile nt = lane>>3, row = lane&7)
      unsigned xbase = (unsigned)__cvta_generic_to_shared(
          &X_[(xs*32 + (lane>>3)*8 + (lane&7))*SDh]);
      #pragma unroll
      for(int kk=0;kk<D/16;kk++){
        unsigned bb0[4], bb1[4];
        ldsm4(bb0, xbase + kk*32);
        ldsm4(bb1, xbase + kk*32 + 16);
        #pragma unroll
        for(int nt=0;nt<4;nt++)
          mma16b(&s[nt*4], wa[kk][0],wa[kk][1],wa[kk][2],wa[kk][3], bb0[nt], bb1[nt]);
      }
      // epilogue: K = 2^min(s2 - qnc - xnc, 0), packed straight into PV A-frags
      __half2 klo[4], khi[4];
      #pragma unroll
      for(int nt=0;nt<4;nt++){
        __half2 xh = *(__half2*)&xn_[xs*32 + nt*8 + 2*p];
        __half2 lo = __floats2half2_rn(s[nt*4+0]-qn0c, s[nt*4+1]-qn0c);
        __half2 hi = __floats2half2_rn(s[nt*4+2]-qn1c, s[nt*4+3]-qn1c);
        lo = __hmin2(__hsub2(lo,xh), zero2);
        hi = __hmin2(__hsub2(hi,xh), zero2);
        klo[nt] = h2exp2(lo); khi[nt] = h2exp2(hi);
      }
      // PV: z += K(16x32) * Lambda(32x32), ldmatrix B-frags
      unsigned lbase = (unsigned)__cvta_generic_to_shared(
          &L_[((lane>>3)*8 + (lane&7))*SDL + xs*32]);
      #pragma unroll
      for(int kc=0;kc<2;kc++){
        unsigned bb0[4], bb1[4];
        ldsm4(bb0, lbase + kc*32);
        ldsm4(bb1, lbase + kc*32 + 16);
        unsigned a0 = *(unsigned*)&klo[2*kc  ];
        unsigned a1 = *(unsigned*)&khi[2*kc  ];
        unsigned a2 = *(unsigned*)&klo[2*kc+1];
        unsigned a3 = *(unsigned*)&khi[2*kc+1];
        #pragma unroll
        for(int nt=0;nt<4;nt++)
          mma16h(&z[nt*4], a0,a1,a2,a3, bb0[nt], bb1[nt]);
      }
    }
  }

  // ---- cross-half z reduction (reuse LT0/LT1 region: 17408 B = 128*34*4) ----
  __syncthreads();
  float* Zr = (float*)LT0;
  if(half_==0){
    #pragma unroll
    for(int nt=0;nt<4;nt++){
      *(float2*)&Zr[(rbase+gr  )*34 + nt*8+2*p] = make_float2(z[nt*4+0], z[nt*4+1]);
      *(float2*)&Zr[(rbase+gr+8)*34 + nt*8+2*p] = make_float2(z[nt*4+2], z[nt*4+3]);
    }
  }
  __syncthreads();
  if(half_==1){
    #pragma unroll
    for(int nt=0;nt<4;nt++){
      float2 a=*(float2*)&Zr[(rbase+gr  )*34 + nt*8+2*p];
      float2 b=*(float2*)&Zr[(rbase+gr+8)*34 + nt*8+2*p];
      *(float2*)&Zout[(size_t)(q0+rbase+gr  )*32 + nt*8+2*p] =
          make_float2(a.x+z[nt*4+0], a.y+z[nt*4+1]);
      *(float2*)&Zout[(size_t)(q0+rbase+gr+8)*32 + nt*8+2*p] =
          make_float2(b.x+z[nt*4+2], b.y+z[nt*4+3]);
    }
  }
}

__global__ __launch_bounds__(512,1) void fused_kernel(){
  if(blockIdx.y==0) fused_body<64>(g_Wm,g_XFm,g_LTm,g_QNm,g_XNm,g_Zm,blockIdx.x);
  else              fused_body<96>(g_Wv,g_XFv,g_LTv,g_QNv,g_XNv,g_Zv,blockIdx.x);
}

// ---------------- 4) finalize ----------------
__global__ __launch_bounds__(256) void final_kernel(
    const float* __restrict__ y_mean, const float* __restrict__ y_var,
    float* __restrict__ out){
  int i = blockIdx.x*256 + threadIdx.x;
  float4 a=*(const float4*)&y_mean[i*4];
  float4 b=*(const float4*)&y_var [i*4];
  float4 zm=*(const float4*)&g_Zm[i*4];
  float4 zv=*(const float4*)&g_Zv[i*4];
  float4 o;
  o.x=a.x+b.x+zm.x+zv.x; o.y=a.y+b.y+zm.y+zv.y;
  o.z=a.z+b.z+zm.z+zv.z; o.w=a.w+b.w+zm.w+zv.w;
  *(float4*)&out[i*4]=o;
}

extern "C" void kernel_launch(void* const* d_in, const int* in_sizes, int n_in,
                              void* d_out, int out_size){
  const float* x_mu   = (const float*)d_in[0];
  const float* y_eta  = (const float*)d_in[1];
  const float* y_mean = (const float*)d_in[2];
  const float* y_var  = (const float*)d_in[3];
  const float* X_mean = (const float*)d_in[4];
  const float* X_var  = (const float*)d_in[5];
  const float* Z_mean = (const float*)d_in[6];
  const float* Z_var  = (const float*)d_in[7];
  const float* kMinv  = (const float*)d_in[8];
  const float* kVinv  = (const float*)d_in[9];
  float* out = (float*)d_out;

  prep_kernel<<<NROW/8, 256>>>(x_mu, y_eta, y_mean, y_var, X_mean, X_var);
  lambda_kernel<<<dim3(NROW/64,4,2), 128>>>(kMinv, kVinv, Z_mean, Z_var);
  reduce_kernel<<<dim3(256,2), 256>>>();
  // smem (D=96): X bf16 2*128*104*2 = 53248; LT fp16 2*32*136*2 = 17408; xn 2*128*2 = 512
  const int FSM = 2*128*104*2 + 2*32*136*2 + 2*128*2;   // 71168 B
  cudaFuncSetAttribute(fused_kernel, cudaFuncAttributeMaxDynamicSharedMemorySize, FSM);
  fused_kernel<<<dim3(64,2), 512, FSM>>>();
  final_kernel<<<NROW*32/4/256, 256>>>(y_mean, y_var, out);
}